// round 6
// baseline (speedup 1.0000x reference)
#include <cuda_runtime.h>
#include <cstdint>
#include <cstddef>

// Problem shape (fixed by the reference):
//   v_feat: (B=32, N=16, T=256, D=512) fp32
//   t_feat: (C=512, D=512) fp32
//   split : int scalar (nonzero -> normalize)
//   out   : (B, C, T) fp32 = einsum('btd,cd->bct', mean_n(norm(v)), norm(t)) / 0.07
#define BB 32
#define NN 16
#define TT 256
#define DD 512
#define CC 512
#define MTOT (BB * TT)            // 8192 rows of v_mean

// Scratch (device globals: allocation inside kernel_launch is forbidden)
__device__ float g_vmean[MTOT * DD];   // 16 MB
__device__ float g_tnorm[CC * DD];     // 1 MB

__device__ __forceinline__ float tf32_rna(float x) {
    unsigned u;
    asm("cvt.rna.tf32.f32 %0, %1;" : "=r"(u) : "f"(x));
    return __uint_as_float(u);
}

// ---------------------------------------------------------------------------
// Kernel 1: per-(b,t) warp: normalize each of the 16 n-rows (L2 over d),
// accumulate, divide by 16, tf32-round, store v_mean row. Pure shfl reduce.
// ---------------------------------------------------------------------------
__global__ void __launch_bounds__(256) reduce_v_kernel(const float* __restrict__ v,
                                                       const int* __restrict__ split) {
    const int w    = (blockIdx.x * 256 + threadIdx.x) >> 5;   // (b,t) index, 0..8191
    const int lane = threadIdx.x & 31;
    const bool donorm = (*split != 0);

    const int b = w >> 8;
    const int t = w & 255;
    const float* vb = v + (((size_t)b * NN) * TT + t) * DD;

    float4 acc0 = make_float4(0.f, 0.f, 0.f, 0.f);
    float4 acc1 = acc0, acc2 = acc0, acc3 = acc0;

#pragma unroll
    for (int n = 0; n < NN; n++) {
        const float4* r = reinterpret_cast<const float4*>(vb + (size_t)n * (TT * DD));
        float4 x0 = r[lane];
        float4 x1 = r[lane + 32];
        float4 x2 = r[lane + 64];
        float4 x3 = r[lane + 96];

        float ss = x0.x * x0.x + x0.y * x0.y + x0.z * x0.z + x0.w * x0.w
                 + x1.x * x1.x + x1.y * x1.y + x1.z * x1.z + x1.w * x1.w
                 + x2.x * x2.x + x2.y * x2.y + x2.z * x2.z + x2.w * x2.w
                 + x3.x * x3.x + x3.y * x3.y + x3.z * x3.z + x3.w * x3.w;
#pragma unroll
        for (int off = 16; off > 0; off >>= 1)
            ss += __shfl_xor_sync(0xffffffffu, ss, off);

        float inv = donorm ? (1.0f / fmaxf(sqrtf(ss), 1e-12f)) : 1.0f;

        acc0.x = fmaf(x0.x, inv, acc0.x); acc0.y = fmaf(x0.y, inv, acc0.y);
        acc0.z = fmaf(x0.z, inv, acc0.z); acc0.w = fmaf(x0.w, inv, acc0.w);
        acc1.x = fmaf(x1.x, inv, acc1.x); acc1.y = fmaf(x1.y, inv, acc1.y);
        acc1.z = fmaf(x1.z, inv, acc1.z); acc1.w = fmaf(x1.w, inv, acc1.w);
        acc2.x = fmaf(x2.x, inv, acc2.x); acc2.y = fmaf(x2.y, inv, acc2.y);
        acc2.z = fmaf(x2.z, inv, acc2.z); acc2.w = fmaf(x2.w, inv, acc2.w);
        acc3.x = fmaf(x3.x, inv, acc3.x); acc3.y = fmaf(x3.y, inv, acc3.y);
        acc3.z = fmaf(x3.z, inv, acc3.z); acc3.w = fmaf(x3.w, inv, acc3.w);
    }

    const float sc = 1.0f / 16.0f;
    float4* o = reinterpret_cast<float4*>(g_vmean + (size_t)w * DD);
    float4 y;
    y.x = tf32_rna(acc0.x * sc); y.y = tf32_rna(acc0.y * sc);
    y.z = tf32_rna(acc0.z * sc); y.w = tf32_rna(acc0.w * sc); o[lane]      = y;
    y.x = tf32_rna(acc1.x * sc); y.y = tf32_rna(acc1.y * sc);
    y.z = tf32_rna(acc1.z * sc); y.w = tf32_rna(acc1.w * sc); o[lane + 32] = y;
    y.x = tf32_rna(acc2.x * sc); y.y = tf32_rna(acc2.y * sc);
    y.z = tf32_rna(acc2.z * sc); y.w = tf32_rna(acc2.w * sc); o[lane + 64] = y;
    y.x = tf32_rna(acc3.x * sc); y.y = tf32_rna(acc3.y * sc);
    y.z = tf32_rna(acc3.z * sc); y.w = tf32_rna(acc3.w * sc); o[lane + 96] = y;
}

// ---------------------------------------------------------------------------
// Kernel 2: normalize t_feat rows, tf32-round.
// ---------------------------------------------------------------------------
__global__ void __launch_bounds__(256) norm_t_kernel(const float* __restrict__ tfeat,
                                                     const int* __restrict__ split) {
    const int w    = (blockIdx.x * 256 + threadIdx.x) >> 5;   // row c, 0..511
    const int lane = threadIdx.x & 31;
    const bool donorm = (*split != 0);

    const float4* r = reinterpret_cast<const float4*>(tfeat + (size_t)w * DD);
    float4 x0 = r[lane], x1 = r[lane + 32], x2 = r[lane + 64], x3 = r[lane + 96];

    float ss = x0.x * x0.x + x0.y * x0.y + x0.z * x0.z + x0.w * x0.w
             + x1.x * x1.x + x1.y * x1.y + x1.z * x1.z + x1.w * x1.w
             + x2.x * x2.x + x2.y * x2.y + x2.z * x2.z + x2.w * x2.w
             + x3.x * x3.x + x3.y * x3.y + x3.z * x3.z + x3.w * x3.w;
#pragma unroll
    for (int off = 16; off > 0; off >>= 1)
        ss += __shfl_xor_sync(0xffffffffu, ss, off);

    float inv = donorm ? (1.0f / fmaxf(sqrtf(ss), 1e-12f)) : 1.0f;

    float4* o = reinterpret_cast<float4*>(g_tnorm + (size_t)w * DD);
    float4 y;
    y.x = tf32_rna(x0.x * inv); y.y = tf32_rna(x0.y * inv);
    y.z = tf32_rna(x0.z * inv); y.w = tf32_rna(x0.w * inv); o[lane]      = y;
    y.x = tf32_rna(x1.x * inv); y.y = tf32_rna(x1.y * inv);
    y.z = tf32_rna(x1.z * inv); y.w = tf32_rna(x1.w * inv); o[lane + 32] = y;
    y.x = tf32_rna(x2.x * inv); y.y = tf32_rna(x2.y * inv);
    y.z = tf32_rna(x2.z * inv); y.w = tf32_rna(x2.w * inv); o[lane + 64] = y;
    y.x = tf32_rna(x3.x * inv); y.y = tf32_rna(x3.y * inv);
    y.z = tf32_rna(x3.z * inv); y.w = tf32_rna(x3.w * inv); o[lane + 96] = y;
}

// ---------------------------------------------------------------------------
// Kernel 3: tf32 GEMM  C[m, c] = vmean[m, :] . tnorm[c, :] / tau,
// stored to out[b, c, t] with m = b*256 + t. BM=BN=128, BK=32, 8 warps,
// warp tile 32(m) x 64(n), mma.sync.m16n8k8.tf32.
// 2-stage smem double buffer, register prefetch, ONE barrier per K-iteration:
//   store into buf^1 never conflicts with readers of buf; the end-of-iteration
//   barrier guarantees everyone left buf before it is overwritten next iter.
// ---------------------------------------------------------------------------
__device__ __forceinline__ void mma_tf32(float* c, const unsigned* a, const unsigned* b) {
    asm volatile(
        "mma.sync.aligned.m16n8k8.row.col.f32.tf32.tf32.f32 "
        "{%0,%1,%2,%3}, {%4,%5,%6,%7}, {%8,%9}, {%0,%1,%2,%3};\n"
        : "+f"(c[0]), "+f"(c[1]), "+f"(c[2]), "+f"(c[3])
        : "r"(a[0]), "r"(a[1]), "r"(a[2]), "r"(a[3]), "r"(b[0]), "r"(b[1]));
}

#define NKT (DD / 32)   // 16 K-tiles

__global__ void __launch_bounds__(256) gemm_kernel(float* __restrict__ out) {
    __shared__ float As[2][128][36];   // pad 36 -> conflict-free fragment LDS
    __shared__ float Bs[2][128][36];

    const int tid  = threadIdx.x;
    const int wid  = tid >> 5;
    const int lane = tid & 31;
    const int gid  = lane >> 2;   // 0..7
    const int tig  = lane & 3;    // 0..3
    const int wm   = (wid & 3) * 32;   // warp m-offset in tile
    const int wn   = (wid >> 2) * 64;  // warp n-offset in tile
    const int mbase = blockIdx.y * 128;
    const int nbase = blockIdx.x * 128;

    // Per-thread gmem/smem staging coordinates (4 float4s each for A and B)
    int srow[4], scol[4];
#pragma unroll
    for (int i = 0; i < 4; i++) {
        int idx = tid + i * 256;      // 0..1023
        srow[i] = idx >> 3;           // 0..127
        scol[i] = (idx & 7) * 4;      // 0,4,...,28
    }

    float c[2][8][4];
#pragma unroll
    for (int mc = 0; mc < 2; mc++)
#pragma unroll
        for (int nc = 0; nc < 8; nc++)
#pragma unroll
            for (int i = 0; i < 4; i++) c[mc][nc][i] = 0.f;

    const float* Ag = g_vmean + (size_t)mbase * DD;
    const float* Bg = g_tnorm + (size_t)nbase * DD;

    float4 av[4], bv[4];

    // Prologue: tile 0 -> smem[0]
#pragma unroll
    for (int i = 0; i < 4; i++) {
        av[i] = *reinterpret_cast<const float4*>(Ag + (size_t)srow[i] * DD + scol[i]);
        bv[i] = *reinterpret_cast<const float4*>(Bg + (size_t)srow[i] * DD + scol[i]);
    }
#pragma unroll
    for (int i = 0; i < 4; i++) {
        *reinterpret_cast<float4*>(&As[0][srow[i]][scol[i]]) = av[i];
        *reinterpret_cast<float4*>(&Bs[0][srow[i]][scol[i]]) = bv[i];
    }
    __syncthreads();

    for (int it = 0; it < NKT; it++) {
        const int buf = it & 1;

        // Prefetch next tile into registers (overlaps with mma block below)
        const bool more = (it + 1 < NKT);
        if (more) {
            const int k0 = (it + 1) * 32;
#pragma unroll
            for (int i = 0; i < 4; i++) {
                av[i] = *reinterpret_cast<const float4*>(Ag + (size_t)srow[i] * DD + k0 + scol[i]);
                bv[i] = *reinterpret_cast<const float4*>(Bg + (size_t)srow[i] * DD + k0 + scol[i]);
            }
        }

        // Compute on smem[buf]
#pragma unroll
        for (int k8 = 0; k8 < 4; k8++) {
            const int ko = k8 * 8;
            unsigned a[2][4], bf[8][2];
#pragma unroll
            for (int mc = 0; mc < 2; mc++) {
                int r0 = wm + mc * 16 + gid;
                a[mc][0] = __float_as_uint(As[buf][r0][ko + tig]);
                a[mc][1] = __float_as_uint(As[buf][r0 + 8][ko + tig]);
                a[mc][2] = __float_as_uint(As[buf][r0][ko + tig + 4]);
                a[mc][3] = __float_as_uint(As[buf][r0 + 8][ko + tig + 4]);
            }
#pragma unroll
            for (int nc = 0; nc < 8; nc++) {
                int rn = wn + nc * 8 + gid;
                bf[nc][0] = __float_as_uint(Bs[buf][rn][ko + tig]);
                bf[nc][1] = __float_as_uint(Bs[buf][rn][ko + tig + 4]);
            }
#pragma unroll
            for (int mc = 0; mc < 2; mc++)
#pragma unroll
                for (int nc = 0; nc < 8; nc++)
                    mma_tf32(c[mc][nc], a[mc], bf[nc]);
        }

        if (more) {
            // Write NEXT tile into the other buffer; no reader conflicts with buf.
#pragma unroll
            for (int i = 0; i < 4; i++) {
                *reinterpret_cast<float4*>(&As[buf ^ 1][srow[i]][scol[i]]) = av[i];
                *reinterpret_cast<float4*>(&Bs[buf ^ 1][srow[i]][scol[i]]) = bv[i];
            }
            __syncthreads();
        }
    }

    // Epilogue: out[b, c, t], m = b*256+t. Per-block b is constant.
    const float s  = 1.0f / 0.07f;
    const int   bB = mbase >> 8;
    const int   tb = mbase & 255;
    float* ob = out + (size_t)bB * (CC * TT) + tb;

#pragma unroll
    for (int mc = 0; mc < 2; mc++) {
#pragma unroll
        for (int nc = 0; nc < 8; nc++) {
            int m0 = wm + mc * 16 + gid;
            int n0 = nbase + wn + nc * 8 + 2 * tig;
            ob[(size_t)n0 * TT + m0]           = c[mc][nc][0] * s;
            ob[(size_t)(n0 + 1) * TT + m0]     = c[mc][nc][1] * s;
            ob[(size_t)n0 * TT + m0 + 8]       = c[mc][nc][2] * s;
            ob[(size_t)(n0 + 1) * TT + m0 + 8] = c[mc][nc][3] * s;
        }
    }
}

// ---------------------------------------------------------------------------
extern "C" void kernel_launch(void* const* d_in, const int* in_sizes, int n_in,
                              void* d_out, int out_size) {
    const float* v     = (const float*)d_in[0];
    const float* tfeat = (const float*)d_in[1];
    const int*   split = (const int*)d_in[2];
    float*       out   = (float*)d_out;

    reduce_v_kernel<<<MTOT / 8, 256>>>(v, split);       // 8192 warps
    norm_t_kernel<<<CC / 8, 256>>>(tfeat, split);       // 512 warps
    gemm_kernel<<<dim3(CC / 128, MTOT / 128), 256>>>(out);
}